// round 6
// baseline (speedup 1.0000x reference)
#include <cuda_runtime.h>
#include <cuda.h>
#include <cstdint>
#include <cstdio>

// ============================================================================
// BlockCirculant == GEMM:  out = x @ M^T + bias
//   M[o,k] = W[o>>7, k>>7, (k-o)&127] * D[k]   (D folded into M)
// sm_100 (plain): legacy mma.sync.m16n8k8.tf32 GEMM.
// CTA tile 128x256x32, 4-stage TMA pipeline, 8 compute warps (64x64 each)
// + 1 TMA producer warp. Warp fragments via ldmatrix against SW128 swizzle.
// ============================================================================

static constexpr int DIMN    = 4096;
static constexpr int TILE_M  = 128;
static constexpr int TILE_N  = 256;
static constexpr int TILE_K  = 32;                  // 32 fp32 = 128B rows (SW128)
static constexpr int STAGES  = 4;
static constexpr int K_ITERS = DIMN / TILE_K;       // 128
static constexpr int A_BYTES = TILE_M * TILE_K * 4; // 16 KB
static constexpr int B_BYTES = TILE_N * TILE_K * 4; // 32 KB
static constexpr int STAGE_BYTES = A_BYTES + B_BYTES; // 48 KB
static constexpr int SMEM_DYN = 1024 + STAGES * STAGE_BYTES; // ~193 KB
static constexpr int MTILES  = DIMN / TILE_M;       // 32
static constexpr int NTILES  = DIMN / TILE_N;       // 16

// 64 MB scratch for the materialized circulant matrix (tf32-rounded fp32)
__device__ float g_M[(size_t)DIMN * DIMN];

// ------------------------------------------------------------ PTX helpers
__device__ __forceinline__ uint32_t smem_u32(const void* p) {
    uint32_t a;
    asm("{ .reg .u64 t; cvta.to.shared.u64 t, %1; cvt.u32.u64 %0, t; }"
        : "=r"(a) : "l"(p));
    return a;
}

__device__ __forceinline__ uint32_t elect_one() {
    uint32_t pred;
    asm volatile(
        "{\n\t.reg .pred p;\n\telect.sync _|p, 0xFFFFFFFF;\n\t"
        "selp.b32 %0, 1, 0, p;\n\t}" : "=r"(pred));
    return pred;
}

#define MBARRIER_INIT(addr, cnt) \
    asm volatile("mbarrier.init.shared.b64 [%0], %1;" \
                 :: "r"((uint32_t)(addr)), "r"((uint32_t)(cnt)) : "memory")

#define MBARRIER_ARRIVE(addr) \
    asm volatile("mbarrier.arrive.shared.b64 _, [%0];" \
                 :: "r"((uint32_t)(addr)) : "memory")

#define MBARRIER_EXPECT_TX(addr, bytes) \
    asm volatile("mbarrier.arrive.expect_tx.shared.b64 _, [%0], %1;" \
                 :: "r"((uint32_t)(addr)), "r"((uint32_t)(bytes)) : "memory")

#define MBARRIER_WAIT_PARITY(addr, parity) do {                                  \
    uint32_t _mbar = (uint32_t)(addr);                                           \
    uint32_t _par  = (uint32_t)(parity);                                         \
    uint32_t _done;                                                              \
    asm volatile(                                                                \
        "{\n\t.reg .pred p;\n\t"                                                 \
        "mbarrier.try_wait.parity.acquire.cta.shared::cta.b64 p, [%1], %2;\n\t"  \
        "selp.b32 %0, 1, 0, p;\n\t}"                                             \
        : "=r"(_done) : "r"(_mbar), "r"(_par) : "memory");                       \
    if (!_done) {                                                                \
        asm volatile(                                                            \
            "{\n\t.reg .pred P1;\n\t"                                            \
            "WAIT_LOOP_%=:\n\t"                                                  \
            "mbarrier.try_wait.parity.acquire.cta.shared::cta.b64 P1, [%0], %1, 0x989680;\n\t" \
            "@P1 bra.uni WAIT_DONE_%=;\n\t"                                      \
            "bra.uni WAIT_LOOP_%=;\n\t"                                          \
            "WAIT_DONE_%=:\n\t}"                                                 \
            :: "r"(_mbar), "r"(_par) : "memory");                                \
    }                                                                            \
} while (0)

#define TMA_LOAD_2D(smem_addr, tmap, cx, cy, mbar)                               \
    asm volatile(                                                                \
        "cp.async.bulk.tensor.2d.shared::cta.global.tile.mbarrier::complete_tx::bytes " \
        "[%0], [%1, {%2, %3}], [%4];"                                            \
        :: "r"((uint32_t)(smem_addr)), "l"(tmap),                                \
           "r"((int32_t)(cx)), "r"((int32_t)(cy)),                               \
           "r"((uint32_t)(mbar)) : "memory")

#define LDSM_X4(d0, d1, d2, d3, addr)                                            \
    asm volatile("ldmatrix.sync.aligned.m8n8.x4.shared.b16 {%0,%1,%2,%3}, [%4];" \
                 : "=r"(d0), "=r"(d1), "=r"(d2), "=r"(d3) : "r"(addr))

__device__ __forceinline__ void mma_tf32(float* c, const uint32_t* a,
                                         const uint32_t* b) {
    asm volatile(
        "mma.sync.aligned.m16n8k8.row.col.f32.tf32.tf32.f32 "
        "{%0,%1,%2,%3}, {%4,%5,%6,%7}, {%8,%9}, {%0,%1,%2,%3};"
        : "+f"(c[0]), "+f"(c[1]), "+f"(c[2]), "+f"(c[3])
        : "r"(a[0]), "r"(a[1]), "r"(a[2]), "r"(a[3]), "r"(b[0]), "r"(b[1]));
}

// ------------------------------------------------------------ prep kernel
// M[o,k] = W[o>>7, k>>7, (k-o)&127] * D[k], rounded to tf32 (rna)
__global__ void bc_build_M(const float* __restrict__ W,
                           const float* __restrict__ Dvec) {
    int idx = blockIdx.x * blockDim.x + threadIdx.x;   // 0 .. 16M-1
    int k = idx & (DIMN - 1);
    int o = idx >> 12;
    int i = o >> 7;
    int j = k >> 7;
    int s = (k - o) & 127;
    float v = W[(i * 32 + j) * 128 + s] * Dvec[k];
    uint32_t u;
    asm("cvt.rna.tf32.f32 %0, %1;" : "=r"(u) : "f"(v));   // tf32 lives in b32
    g_M[idx] = __uint_as_float(u);
}

// ------------------------------------------------------------ GEMM kernel
// 288 threads: warps 0-7 compute (2M x 4N grid, warp tile 64x64), warp 8 TMA.
__global__ void __launch_bounds__(288, 1)
bc_gemm(const __grid_constant__ CUtensorMap tma_a,
        const __grid_constant__ CUtensorMap tma_b,
        const float* __restrict__ bias,
        float* __restrict__ out) {
    extern __shared__ char smem[];
    const uint32_t raw = smem_u32(smem);
    // Layout: [raw, raw+1024) barriers, stage tiles at 1024B alignment after.
    const uint32_t bar_full  = ((raw + 15u) & ~7u);
    const uint32_t bar_empty = bar_full + 8 * STAGES;
    const uint32_t tiles     = (raw + 1024u + 1023u) & ~1023u;

    const int tid  = threadIdx.x;
    const int wid  = tid >> 5;
    const int lane = tid & 31;

    // grouped rasterization for L2 reuse: groups of 8 M-tiles x all N-tiles
    const int bid = blockIdx.x;
    constexpr int GM = 8;
    const int grp = bid / (GM * NTILES);
    const int rem = bid % (GM * NTILES);
    const int mt  = grp * GM + (rem % GM);
    const int nt  = rem / GM;

    if (tid == 0) {
        for (int s = 0; s < STAGES; s++) {
            MBARRIER_INIT(bar_full + 8 * s, 1);    // tx-based
            MBARRIER_INIT(bar_empty + 8 * s, 8);   // one arrive per compute warp
        }
        asm volatile("fence.proxy.async.shared::cta;" ::: "memory");
    }
    __syncthreads();

    if (wid == 8) {
        // ---------------- TMA producer warp ----------------
        if (elect_one()) {
            int stage = 0, phase = 1;   // parity 1: first STAGES empty-waits pass
            for (int kt = 0; kt < K_ITERS; kt++) {
                MBARRIER_WAIT_PARITY(bar_empty + 8 * stage, phase);
                MBARRIER_EXPECT_TX(bar_full + 8 * stage, STAGE_BYTES);
                uint32_t dst = tiles + stage * STAGE_BYTES;
                TMA_LOAD_2D(dst,           &tma_a, kt * TILE_K, mt * TILE_M, bar_full + 8 * stage);
                TMA_LOAD_2D(dst + A_BYTES, &tma_b, kt * TILE_K, nt * TILE_N, bar_full + 8 * stage);
                if (++stage == STAGES) { stage = 0; phase ^= 1; }
            }
        }
        return;
    }

    // ---------------- compute warps (0-7) ----------------
    const int wm = wid & 1;          // 2 warp rows in M
    const int wn = wid >> 1;         // 4 warp cols in N
    const int mo = wm * 64;          // warp M offset within CTA tile
    const int no = wn * 64;          // warp N offset within CTA tile

    // ldmatrix base offsets per k-step (SW128 swizzle: 16B chunk ^= row&7).
    // mo/no and tile sub-offsets are multiples of 8, so row&7 == r for all
    // fragments: the swizzle term is invariant in i/p, and +i*2048 / +p*2048
    // fold into LDSM immediates.
    uint32_t offA0[4], offB0[4];
    {
        const int t = lane >> 3, r = lane & 7;
#pragma unroll
        for (int ks = 0; ks < 4; ks++) {
            {   // A: row = mo + (t&1)*8 + r, chunk = ks*2 + (t>>1)
                int row = mo + (t & 1) * 8 + r;
                int chunk = ks * 2 + (t >> 1);
                offA0[ks] = row * 128 + (((chunk ^ r)) << 4);
            }
            {   // B: row = no + (t>>1)*8 + r, chunk = ks*2 + (t&1)
                int row = no + (t >> 1) * 8 + r;
                int chunk = ks * 2 + (t & 1);
                offB0[ks] = row * 128 + (((chunk ^ r)) << 4);
            }
        }
    }

    float c[4][8][4];
#pragma unroll
    for (int i = 0; i < 4; i++)
#pragma unroll
        for (int j = 0; j < 8; j++)
#pragma unroll
            for (int q = 0; q < 4; q++) c[i][j][q] = 0.0f;

    int stage = 0, phase = 0;
#pragma unroll 1
    for (int kt = 0; kt < K_ITERS; kt++) {
        MBARRIER_WAIT_PARITY(bar_full + 8 * stage, phase);
        const uint32_t sa = tiles + stage * STAGE_BYTES;
        const uint32_t sb = sa + A_BYTES;

#pragma unroll
        for (int ks = 0; ks < 4; ks++) {
            uint32_t a[4][4], b[8][2];
#pragma unroll
            for (int i = 0; i < 4; i++)
                LDSM_X4(a[i][0], a[i][1], a[i][2], a[i][3],
                        sa + offA0[ks] + i * 2048);
#pragma unroll
            for (int p = 0; p < 4; p++)
                LDSM_X4(b[2 * p][0], b[2 * p][1], b[2 * p + 1][0], b[2 * p + 1][1],
                        sb + offB0[ks] + p * 2048);
#pragma unroll
            for (int i = 0; i < 4; i++)
#pragma unroll
                for (int j = 0; j < 8; j++)
                    mma_tf32(c[i][j], a[i], b[j]);
        }
        if (elect_one()) MBARRIER_ARRIVE(bar_empty + 8 * stage);
        if (++stage == STAGES) { stage = 0; phase ^= 1; }
    }

    // ---------------- epilogue: bias add + store ----------------
    const int grow0 = mt * TILE_M + mo;
    const int gcol0 = nt * TILE_N + no;
    const int g   = lane >> 2;
    const int tig = lane & 3;
#pragma unroll
    for (int i = 0; i < 4; i++) {
        const int r0 = grow0 + i * 16 + g;
        const int r1 = r0 + 8;
        float* out0 = out + (size_t)r0 * DIMN;
        float* out1 = out + (size_t)r1 * DIMN;
#pragma unroll
        for (int j = 0; j < 8; j++) {
            const int col = gcol0 + j * 8 + tig * 2;
            const float2 bz = *reinterpret_cast<const float2*>(bias + col);
            float2 v0 = {c[i][j][0] + bz.x, c[i][j][1] + bz.y};
            float2 v1 = {c[i][j][2] + bz.x, c[i][j][3] + bz.y};
            *reinterpret_cast<float2*>(out0 + col) = v0;
            *reinterpret_cast<float2*>(out1 + col) = v1;
        }
    }
}

// ------------------------------------------------------------ host launch
extern "C" void kernel_launch(void* const* d_in, const int* in_sizes, int n_in,
                              void* d_out, int out_size) {
    const float* x    = (const float*)d_in[0];
    const float* W    = (const float*)d_in[1];
    const float* Dv   = (const float*)d_in[2];
    const float* bias = (const float*)d_in[3];
    float* out        = (float*)d_out;

    void* m_ptr = nullptr;
    cudaGetSymbolAddress(&m_ptr, g_M);

    // cuTensorMapEncodeTiled via driver entry point (no -lcuda needed)
    typedef CUresult (*EncodeFn)(CUtensorMap*, CUtensorMapDataType, cuuint32_t, void*,
                                 const cuuint64_t*, const cuuint64_t*, const cuuint32_t*,
                                 const cuuint32_t*, CUtensorMapInterleave, CUtensorMapSwizzle,
                                 CUtensorMapL2promotion, CUtensorMapFloatOOBfill);
    void* fn = nullptr;
    cudaDriverEntryPointQueryResult qr;
    cudaGetDriverEntryPoint("cuTensorMapEncodeTiled", &fn, cudaEnableDefault, &qr);
    EncodeFn encode = (EncodeFn)fn;
    if (!encode) { fprintf(stderr, "no cuTensorMapEncodeTiled\n"); return; }

    cuuint64_t dims[2]    = {(cuuint64_t)DIMN, (cuuint64_t)DIMN};
    cuuint64_t strides[1] = {(cuuint64_t)DIMN * sizeof(float)};
    cuuint32_t es[2]      = {1, 1};

    CUtensorMap ta{}, tb{};
    cuuint32_t boxA[2] = {TILE_K, TILE_M};   // 128B x 128 rows
    cuuint32_t boxB[2] = {TILE_K, TILE_N};   // 128B x 256 rows
    encode(&ta, CU_TENSOR_MAP_DATA_TYPE_FLOAT32, 2, (void*)x, dims, strides, boxA, es,
           CU_TENSOR_MAP_INTERLEAVE_NONE, CU_TENSOR_MAP_SWIZZLE_128B,
           CU_TENSOR_MAP_L2_PROMOTION_L2_128B, CU_TENSOR_MAP_FLOAT_OOB_FILL_NONE);
    encode(&tb, CU_TENSOR_MAP_DATA_TYPE_FLOAT32, 2, m_ptr, dims, strides, boxB, es,
           CU_TENSOR_MAP_INTERLEAVE_NONE, CU_TENSOR_MAP_SWIZZLE_128B,
           CU_TENSOR_MAP_L2_PROMOTION_L2_128B, CU_TENSOR_MAP_FLOAT_OOB_FILL_NONE);

    cudaFuncSetAttribute(bc_gemm, cudaFuncAttributeMaxDynamicSharedMemorySize, SMEM_DYN);

    bc_build_M<<<(DIMN * DIMN) / 256, 256>>>(W, Dv);
    bc_gemm<<<MTILES * NTILES, 288, SMEM_DYN>>>(ta, tb, bias, out);
}

// round 8
// speedup vs baseline: 2.3132x; 2.3132x over previous
#include <cuda_runtime.h>
#include <cuda.h>
#include <cstdint>
#include <cstdio>
#include <math.h>

// ============================================================================
// BlockCirculant via DFT factorization (63x fewer FLOPs than dense GEMM):
//   out[b, i*128+t] = ifft_t( sum_j fft(x_d block j) * conj(fft(W[i,j])) ) + bias
// Pipeline (all GEMMs legacy mma.sync m16n8k8 tf32):
//   P: build twiddles, F_j (fwd DFT * D, hi/lo split), Op[fs] (64x64 per-freq
//      block mix from W), B3 (inv DFT, hi/lo split)
//   G1: X1[j][b][n]   = x[b][j*128+s] @ F_j[n][s]^T      (3xTF32, K=128)
//   T1: Xg[fs][b][2j+c] = X1[j][b][2fs+c]                (float2 transpose)
//   G2: C[fs][b][2i+c]  = Xg[fs][b][.] @ Op[fs]^T        (tf32, K=64 - only lossy stage)
//   T2: Z[b*32+i][2fs+c] = C[fs][b][2i+c]                (float2 transpose)
//   G3: out[r][t]       = Z[r][.] @ B3[t][.]^T + bias    (3xTF32, K=128)
// Freq packing: n = 2*fs + c; slot fs=0 carries (f=0, f=64[Nyquist]) real bins.
// ============================================================================

static constexpr int DIMN = 4096;

// 64 MB ping-pong buffers + transform matrices
__device__ float  g_bufA[(size_t)DIMN * DIMN];
__device__ float  g_bufB[(size_t)DIMN * DIMN];
__device__ float  g_Fj_hi[32 * 128 * 128];
__device__ float  g_Fj_lo[32 * 128 * 128];
__device__ float  g_Op[64 * 64 * 64];
__device__ float  g_B3_hi[128 * 128];
__device__ float  g_B3_lo[128 * 128];
__device__ float2 g_tw[128];

// ------------------------------------------------------------ PTX helpers
__device__ __forceinline__ uint32_t smem_u32(const void* p) {
    uint32_t a;
    asm("{ .reg .u64 t; cvta.to.shared.u64 t, %1; cvt.u32.u64 %0, t; }"
        : "=r"(a) : "l"(p));
    return a;
}
__device__ __forceinline__ uint32_t elect_one() {
    uint32_t pred;
    asm volatile(
        "{\n\t.reg .pred p;\n\telect.sync _|p, 0xFFFFFFFF;\n\t"
        "selp.b32 %0, 1, 0, p;\n\t}" : "=r"(pred));
    return pred;
}
#define MBARRIER_INIT(addr, cnt) \
    asm volatile("mbarrier.init.shared.b64 [%0], %1;" \
                 :: "r"((uint32_t)(addr)), "r"((uint32_t)(cnt)) : "memory")
#define MBARRIER_EXPECT_TX(addr, bytes) \
    asm volatile("mbarrier.arrive.expect_tx.shared.b64 _, [%0], %1;" \
                 :: "r"((uint32_t)(addr)), "r"((uint32_t)(bytes)) : "memory")
#define MBARRIER_WAIT_PARITY(addr, parity) do {                                  \
    uint32_t _mbar = (uint32_t)(addr);                                           \
    uint32_t _par  = (uint32_t)(parity);                                         \
    uint32_t _done;                                                              \
    asm volatile(                                                                \
        "{\n\t.reg .pred p;\n\t"                                                 \
        "mbarrier.try_wait.parity.acquire.cta.shared::cta.b64 p, [%1], %2;\n\t"  \
        "selp.b32 %0, 1, 0, p;\n\t}"                                             \
        : "=r"(_done) : "r"(_mbar), "r"(_par) : "memory");                       \
    if (!_done) {                                                                \
        asm volatile(                                                            \
            "{\n\t.reg .pred P1;\n\t"                                            \
            "WAIT_LOOP_%=:\n\t"                                                  \
            "mbarrier.try_wait.parity.acquire.cta.shared::cta.b64 P1, [%0], %1, 0x989680;\n\t" \
            "@P1 bra.uni WAIT_DONE_%=;\n\t"                                      \
            "bra.uni WAIT_LOOP_%=;\n\t"                                          \
            "WAIT_DONE_%=:\n\t}"                                                 \
            :: "r"(_mbar), "r"(_par) : "memory");                                \
    }                                                                            \
} while (0)
#define TMA_LOAD_2D(smem_addr, tmap, cx, cy, mbar)                               \
    asm volatile(                                                                \
        "cp.async.bulk.tensor.2d.shared::cta.global.tile.mbarrier::complete_tx::bytes " \
        "[%0], [%1, {%2, %3}], [%4];"                                            \
        :: "r"((uint32_t)(smem_addr)), "l"(tmap),                                \
           "r"((int32_t)(cx)), "r"((int32_t)(cy)),                               \
           "r"((uint32_t)(mbar)) : "memory")
#define LDSM_X4(d0, d1, d2, d3, addr)                                            \
    asm volatile("ldmatrix.sync.aligned.m8n8.x4.shared.b16 {%0,%1,%2,%3}, [%4];" \
                 : "=r"(d0), "=r"(d1), "=r"(d2), "=r"(d3) : "r"(addr))

__device__ __forceinline__ void mma_tf32(float* c, const uint32_t* a,
                                         const uint32_t* b) {
    asm volatile(
        "mma.sync.aligned.m16n8k8.row.col.f32.tf32.tf32.f32 "
        "{%0,%1,%2,%3}, {%4,%5,%6,%7}, {%8,%9}, {%0,%1,%2,%3};"
        : "+f"(c[0]), "+f"(c[1]), "+f"(c[2]), "+f"(c[3])
        : "r"(a[0]), "r"(a[1]), "r"(a[2]), "r"(a[3]), "r"(b[0]), "r"(b[1]));
}
__device__ __forceinline__ float tf32r(float v) {
    uint32_t u;
    asm("cvt.rna.tf32.f32 %0, %1;" : "=r"(u) : "f"(v));
    return __uint_as_float(u);
}

// ------------------------------------------------------------ prep kernels
__global__ void bc_tw() {
    int t = threadIdx.x;
    double ang = (3.14159265358979323846 / 64.0) * t;   // 2*pi*t/128
    g_tw[t] = make_float2((float)cos(ang), (float)sin(ang));
}

// F_j[j][n][s] = F1[n][s] * D[j*128+s]; hi/lo tf32 split
__global__ void bc_build_fj(const float* __restrict__ Dvec) {
    int idx = blockIdx.x * 256 + threadIdx.x;      // 0..524287
    int j = idx >> 14;
    int n = (idx >> 7) & 127;
    int s = idx & 127;
    float base;
    if (n == 0)      base = 1.0f;
    else if (n == 1) base = (s & 1) ? -1.0f : 1.0f;           // f=64 (Nyquist)
    else {
        int f = n >> 1;
        float2 w = g_tw[(f * s) & 127];
        base = (n & 1) ? w.y : w.x;                           // sin : cos
    }
    float v  = base * Dvec[j * 128 + s];
    float hi = tf32r(v);
    g_Fj_hi[idx] = hi;
    g_Fj_lo[idx] = tf32r(v - hi);
}

// Op[fs][n=2i+c][k=2j+c'] from aW/bW of W[i][j][.]
__global__ void bc_build_op(const float* __restrict__ W) {
    int tid = blockIdx.x * 256 + threadIdx.x;      // 0..65535
    int fs = tid >> 10;
    int i  = (tid >> 5) & 31;
    int j  = tid & 31;
    const float* w = W + (i * 32 + j) * 128;
    float* op = g_Op + (size_t)fs * 4096;          // [64][64] slab
    if (fs == 0) {
        float a0 = 0.f, a64 = 0.f;
        for (int u = 0; u < 128; u++) {
            float wu = w[u];
            a0  += wu;
            a64 += (u & 1) ? -wu : wu;
        }
        op[(2 * i) * 64 + 2 * j]         = tf32r(a0);
        op[(2 * i) * 64 + 2 * j + 1]     = 0.f;
        op[(2 * i + 1) * 64 + 2 * j]     = 0.f;
        op[(2 * i + 1) * 64 + 2 * j + 1] = tf32r(a64);
    } else {
        float aw = 0.f, bw = 0.f;
        for (int u = 0; u < 128; u++) {
            float2 t = g_tw[(fs * u) & 127];
            float wu = w[u];
            aw += wu * t.x;
            bw += wu * t.y;
        }
        // Y_re = aX*aW + bX*bW ; Y_im = aX*bW - bX*aW
        op[(2 * i) * 64 + 2 * j]         = tf32r(aw);
        op[(2 * i) * 64 + 2 * j + 1]     = tf32r(bw);
        op[(2 * i + 1) * 64 + 2 * j]     = tf32r(bw);
        op[(2 * i + 1) * 64 + 2 * j + 1] = tf32r(-aw);
    }
}

// B3[t][n'] inverse transform; hi/lo split
__global__ void bc_build_b3() {
    int idx = blockIdx.x * 256 + threadIdx.x;      // 0..16383
    int t = idx >> 7;
    int n = idx & 127;
    float v;
    if (n == 0)      v = 1.0f / 128.0f;
    else if (n == 1) v = ((t & 1) ? -1.0f : 1.0f) / 128.0f;
    else {
        int f = n >> 1;
        float2 w = g_tw[(f * t) & 127];
        v = ((n & 1) ? -w.y : w.x) * (2.0f / 128.0f);   // cos(+), sin(-)
    }
    float hi = tf32r(v);
    g_B3_hi[idx] = hi;
    g_B3_lo[idx] = tf32r(v - hi);
}

// ------------------------------------------------------------ split GEMM
// C[128 x 128] = A[128 x 128] @ B^T with 3xTF32 (B pre-split hi/lo).
// 288 thr: 8 compute warps (warp tile 64x32), warp 8 = TMA producer.
// Used for G1 (grid 32x32, A=x, B=Fj, out=X1) and G3 (grid 1024x1, A=Z,
// B=B3, out=out with bias).
static constexpr int GK_ITERS   = 4;      // K=128 in 4 chunks of 32
static constexpr int G_ABYTES   = 128 * 32 * 4;          // 16 KB
static constexpr int G_STAGE    = 3 * G_ABYTES;          // A + Bhi + Blo = 48 KB
static constexpr int SMEM_G     = 2048 + GK_ITERS * G_STAGE;  // ~194 KB

__global__ void __launch_bounds__(288, 1)
bc_split_gemm(const __grid_constant__ CUtensorMap tma_a,
              const __grid_constant__ CUtensorMap tma_bh,
              const __grid_constant__ CUtensorMap tma_bl,
              float* __restrict__ outp,
              const float* __restrict__ bias) {
    extern __shared__ char smem[];
    const uint32_t raw      = smem_u32(smem);
    const uint32_t bar_full = (raw + 15u) & ~7u;                 // 4 barriers
    const uint32_t tiles    = (raw + 1024u + 1023u) & ~1023u;

    const int tid  = threadIdx.x;
    const int wid  = tid >> 5;
    const int lane = tid & 31;
    const int mt   = blockIdx.x;
    const int jb   = blockIdx.y;

    if (tid == 0) {
        for (int s = 0; s < GK_ITERS; s++) MBARRIER_INIT(bar_full + 8 * s, 1);
        asm volatile("fence.proxy.async.shared::cta;" ::: "memory");
    }
    __syncthreads();

    if (wid == 8) {
        if (elect_one()) {
            // 4 stages = 4 k-iters: fire everything, no reuse, no backpressure
            for (int kt = 0; kt < GK_ITERS; kt++) {
                MBARRIER_EXPECT_TX(bar_full + 8 * kt, G_STAGE);
                uint32_t dst = tiles + kt * G_STAGE;
                TMA_LOAD_2D(dst,                &tma_a,  jb * 128 + kt * 32, mt * 128, bar_full + 8 * kt);
                TMA_LOAD_2D(dst + G_ABYTES,     &tma_bh, kt * 32,            jb * 128, bar_full + 8 * kt);
                TMA_LOAD_2D(dst + 2 * G_ABYTES, &tma_bl, kt * 32,            jb * 128, bar_full + 8 * kt);
            }
        }
        return;
    }

    const int wm = wid & 1;          // 2 warp rows (M)
    const int wn = wid >> 1;         // 4 warp cols (N)
    const int mo = wm * 64;
    const int no = wn * 32;

    // ldmatrix offsets (SW128: 16B chunk ^= row&7; row&7 == rr here)
    uint32_t offA[4], offB[4];
    {
        const int t = lane >> 3, rr = lane & 7;
#pragma unroll
        for (int ks = 0; ks < 4; ks++) {
            int rowA = mo + (t & 1) * 8 + rr;
            int chA  = ks * 2 + (t >> 1);
            offA[ks] = rowA * 128 + ((chA ^ rr) << 4);
            int rowB = no + (t >> 1) * 8 + rr;
            int chB  = ks * 2 + (t & 1);
            offB[ks] = rowB * 128 + ((chB ^ rr) << 4);
        }
    }

    float c[4][4][4];
#pragma unroll
    for (int i = 0; i < 4; i++)
#pragma unroll
        for (int j = 0; j < 4; j++)
#pragma unroll
            for (int q = 0; q < 4; q++) c[i][j][q] = 0.0f;

#pragma unroll 1
    for (int kt = 0; kt < GK_ITERS; kt++) {
        MBARRIER_WAIT_PARITY(bar_full + 8 * kt, 0);
        const uint32_t sa  = tiles + kt * G_STAGE;
        const uint32_t sbh = sa + G_ABYTES;
        const uint32_t sbl = sa + 2 * G_ABYTES;
#pragma unroll
        for (int ks = 0; ks < 4; ks++) {
            uint32_t araw[4][4], bh[4][2], bl[4][2];
#pragma unroll
            for (int i = 0; i < 4; i++)
                LDSM_X4(araw[i][0], araw[i][1], araw[i][2], araw[i][3],
                        sa + offA[ks] + i * 2048);
            LDSM_X4(bh[0][0], bh[0][1], bh[1][0], bh[1][1], sbh + offB[ks]);
            LDSM_X4(bh[2][0], bh[2][1], bh[3][0], bh[3][1], sbh + offB[ks] + 2048);
            LDSM_X4(bl[0][0], bl[0][1], bl[1][0], bl[1][1], sbl + offB[ks]);
            LDSM_X4(bl[2][0], bl[2][1], bl[3][0], bl[3][1], sbl + offB[ks] + 2048);
            // in-register 3xTF32 split of A
            uint32_t ah[4][4], al[4][4];
#pragma unroll
            for (int i = 0; i < 4; i++)
#pragma unroll
                for (int q = 0; q < 4; q++) {
                    float v = __uint_as_float(araw[i][q]);
                    uint32_t h;
                    asm("cvt.rna.tf32.f32 %0, %1;" : "=r"(h) : "f"(v));
                    float r2 = v - __uint_as_float(h);
                    uint32_t l;
                    asm("cvt.rna.tf32.f32 %0, %1;" : "=r"(l) : "f"(r2));
                    ah[i][q] = h; al[i][q] = l;
                }
#pragma unroll
            for (int i = 0; i < 4; i++)
#pragma unroll
                for (int j = 0; j < 4; j++) {
                    mma_tf32(c[i][j], al[i], bh[j]);
                    mma_tf32(c[i][j], ah[i], bl[j]);
                    mma_tf32(c[i][j], ah[i], bh[j]);
                }
        }
    }

    // epilogue (ldc = 128); bias indexed by (row & 31)*128 + col (G3 only)
    const size_t rowbase = (size_t)jb * 4096 + (size_t)mt * 128;
    const int g   = lane >> 2;
    const int tig = lane & 3;
#pragma unroll
    for (int i = 0; i < 4; i++) {
        const int r0l = mo + i * 16 + g;
        float* o0 = outp + (rowbase + r0l) * 128;
        float* o1 = o0 + 8 * 128;
#pragma unroll
        for (int j = 0; j < 4; j++) {
            const int col = no + j * 8 + tig * 2;
            float2 v0 = {c[i][j][0], c[i][j][1]};
            float2 v1 = {c[i][j][2], c[i][j][3]};
            if (bias) {
                const float* b0 = bias + (r0l & 31) * 128 + col;
                const float* b1 = bias + ((r0l + 8) & 31) * 128 + col;
                v0.x += b0[0]; v0.y += b0[1];
                v1.x += b1[0]; v1.y += b1[1];
            }
            *reinterpret_cast<float2*>(o0 + col) = v0;
            *reinterpret_cast<float2*>(o1 + col) = v1;
        }
    }
}

// ------------------------------------------------------------ G2 kernel
// Per fs: C[256 x 64] += Xg[256 x 64] @ Op[fs]^T, K=64 (two 32-col halves).
// 256 thr = 8 compute warps (warp tile 32x64); thread 0 issues TMA.
static constexpr int G2_SMEM = 2048 + 81920;

__global__ void __launch_bounds__(256, 2)
bc_g2(const __grid_constant__ CUtensorMap tma_xg,
      const __grid_constant__ CUtensorMap tma_op,
      float* __restrict__ outp) {
    extern __shared__ char smem[];
    const uint32_t raw   = smem_u32(smem);
    const uint32_t bar   = (raw + 15u) & ~7u;
    const uint32_t tiles = (raw + 1024u + 1023u) & ~1023u;

    const int tid  = threadIdx.x;
    const int w    = tid >> 5;
    const int lane = tid & 31;
    const int mt   = blockIdx.x;     // 16 b-tiles of 256
    const int fs   = blockIdx.y;     // 64 freq slots

    if (tid == 0) {
        MBARRIER_INIT(bar, 1);
        asm volatile("fence.proxy.async.shared::cta;" ::: "memory");
    }
    __syncthreads();
    if (tid == 0) {
        MBARRIER_EXPECT_TX(bar, 81920);
        int ya = fs * 4096 + mt * 256;
        TMA_LOAD_2D(tiles,         &tma_xg, 0,  ya,      bar);
        TMA_LOAD_2D(tiles + 32768, &tma_xg, 32, ya,      bar);
        TMA_LOAD_2D(tiles + 65536, &tma_op, 0,  fs * 64, bar);
        TMA_LOAD_2D(tiles + 73728, &tma_op, 32, fs * 64, bar);
    }

    uint32_t offA[4], offB[4];
    {
        const int t = lane >> 3, rr = lane & 7;
#pragma unroll
        for (int kk = 0; kk < 4; kk++) {
            int rowA = w * 32 + (t & 1) * 8 + rr;
            int chA  = kk * 2 + (t >> 1);
            offA[kk] = rowA * 128 + ((chA ^ rr) << 4);
            int rowB = (t >> 1) * 8 + rr;
            int chB  = kk * 2 + (t & 1);
            offB[kk] = rowB * 128 + ((chB ^ rr) << 4);
        }
    }

    float c[2][8][4];
#pragma unroll
    for (int i = 0; i < 2; i++)
#pragma unroll
        for (int j = 0; j < 8; j++)
#pragma unroll
            for (int q = 0; q < 4; q++) c[i][j][q] = 0.0f;

    MBARRIER_WAIT_PARITY(bar, 0);

#pragma unroll
    for (int h = 0; h < 2; h++) {
        const uint32_t sa = tiles + h * 32768;
        const uint32_t sb = tiles + 65536 + h * 8192;
#pragma unroll
        for (int kk = 0; kk < 4; kk++) {
            uint32_t araw[2][4], a[2][4], b[8][2];
#pragma unroll
            for (int i = 0; i < 2; i++)
                LDSM_X4(araw[i][0], araw[i][1], araw[i][2], araw[i][3],
                        sa + offA[kk] + i * 2048);
#pragma unroll
            for (int np = 0; np < 4; np++)
                LDSM_X4(b[2 * np][0], b[2 * np][1], b[2 * np + 1][0], b[2 * np + 1][1],
                        sb + offB[kk] + np * 2048);
#pragma unroll
            for (int i = 0; i < 2; i++)
#pragma unroll
                for (int q = 0; q < 4; q++) {
                    float v = __uint_as_float(araw[i][q]);
                    asm("cvt.rna.tf32.f32 %0, %1;" : "=r"(a[i][q]) : "f"(v));
                }
#pragma unroll
            for (int i = 0; i < 2; i++)
#pragma unroll
                for (int j = 0; j < 8; j++)
                    mma_tf32(c[i][j], a[i], b[j]);
        }
    }

    // epilogue: C[fs][b][n], row = mt*256 + w*32 + ..., ld = 64
    const size_t base = (size_t)fs * 262144 + ((size_t)mt * 256 + w * 32) * 64;
    const int g   = lane >> 2;
    const int tig = lane & 3;
#pragma unroll
    for (int i = 0; i < 2; i++) {
        float* o0 = outp + base + (i * 16 + g) * 64;
        float* o1 = o0 + 8 * 64;
#pragma unroll
        for (int j = 0; j < 8; j++) {
            const int col = j * 8 + tig * 2;
            *reinterpret_cast<float2*>(o0 + col) = make_float2(c[i][j][0], c[i][j][1]);
            *reinterpret_cast<float2*>(o1 + col) = make_float2(c[i][j][2], c[i][j][3]);
        }
    }
}

// ------------------------------------------------------------ transpose
// dst[b*dB + q*dQ + p] = src[p*sP + b*sB + q]   (float2 elements)
__global__ void __launch_bounds__(256)
bc_transpose(const float2* __restrict__ src, float2* __restrict__ dst,
             int sP, int sB, int dQ, int dB, int qtiles) {
    __shared__ float sx[32][33];
    __shared__ float sy[32][33];
    const int b  = blockIdx.x;
    const int pt = blockIdx.y / qtiles;
    const int qt = blockIdx.y % qtiles;
    const int tx = threadIdx.x & 31;
    const int ty = threadIdx.x >> 5;   // 0..7
    const float2* s = src + (size_t)b * sB + (size_t)(pt * 32) * sP + qt * 32;
    float2*       d = dst + (size_t)b * dB + (size_t)(qt * 32) * dQ + pt * 32;
#pragma unroll
    for (int k = 0; k < 4; k++) {
        int p = ty + k * 8;
        float2 v = s[(size_t)p * sP + tx];
        sx[p][tx] = v.x;
        sy[p][tx] = v.y;
    }
    __syncthreads();
#pragma unroll
    for (int k = 0; k < 4; k++) {
        int q = ty + k * 8;
        d[(size_t)q * dQ + tx] = make_float2(sx[tx][q], sy[tx][q]);
    }
}

// ------------------------------------------------------------ host launch
extern "C" void kernel_launch(void* const* d_in, const int* in_sizes, int n_in,
                              void* d_out, int out_size) {
    const float* x    = (const float*)d_in[0];
    const float* W    = (const float*)d_in[1];
    const float* Dv   = (const float*)d_in[2];
    const float* bias = (const float*)d_in[3];
    float* out        = (float*)d_out;

    void *pA, *pB, *pFh, *pFl, *pOp, *pB3h, *pB3l;
    cudaGetSymbolAddress(&pA,   g_bufA);
    cudaGetSymbolAddress(&pB,   g_bufB);
    cudaGetSymbolAddress(&pFh,  g_Fj_hi);
    cudaGetSymbolAddress(&pFl,  g_Fj_lo);
    cudaGetSymbolAddress(&pOp,  g_Op);
    cudaGetSymbolAddress(&pB3h, g_B3_hi);
    cudaGetSymbolAddress(&pB3l, g_B3_lo);

    typedef CUresult (*EncodeFn)(CUtensorMap*, CUtensorMapDataType, cuuint32_t, void*,
                                 const cuuint64_t*, const cuuint64_t*, const cuuint32_t*,
                                 const cuuint32_t*, CUtensorMapInterleave, CUtensorMapSwizzle,
                                 CUtensorMapL2promotion, CUtensorMapFloatOOBfill);
    void* fn = nullptr;
    cudaDriverEntryPointQueryResult qr;
    cudaGetDriverEntryPoint("cuTensorMapEncodeTiled", &fn, cudaEnableDefault, &qr);
    EncodeFn encode = (EncodeFn)fn;
    if (!encode) { fprintf(stderr, "no cuTensorMapEncodeTiled\n"); return; }

    auto enc2d = [&](CUtensorMap* tm, void* ptr, uint64_t cols, uint64_t rows,
                     uint32_t bx, uint32_t by) {
        cuuint64_t dims[2]    = {cols, rows};
        cuuint64_t strides[1] = {cols * sizeof(float)};
        cuuint32_t box[2]     = {bx, by};
        cuuint32_t es[2]      = {1, 1};
        encode(tm, CU_TENSOR_MAP_DATA_TYPE_FLOAT32, 2, ptr, dims, strides, box, es,
               CU_TENSOR_MAP_INTERLEAVE_NONE, CU_TENSOR_MAP_SWIZZLE_128B,
               CU_TENSOR_MAP_L2_PROMOTION_L2_128B, CU_TENSOR_MAP_FLOAT_OOB_FILL_NONE);
    };

    CUtensorMap tm_x, tm_fh, tm_fl, tm_z, tm_b3h, tm_b3l, tm_xg, tm_op;
    enc2d(&tm_x,   (void*)x, 4096, 4096,   32, 128);   // G1 A
    enc2d(&tm_fh,  pFh,      128,  4096,   32, 128);   // G1 B hi
    enc2d(&tm_fl,  pFl,      128,  4096,   32, 128);   // G1 B lo
    enc2d(&tm_z,   pB,       128,  131072, 32, 128);   // G3 A (Z in bufB)
    enc2d(&tm_b3h, pB3h,     128,  128,    32, 128);   // G3 B hi
    enc2d(&tm_b3l, pB3l,     128,  128,    32, 128);   // G3 B lo
    enc2d(&tm_xg,  pB,       64,   262144, 32, 256);   // G2 A (Xg in bufB)
    enc2d(&tm_op,  pOp,      64,   4096,   32, 64);    // G2 B

    cudaFuncSetAttribute(bc_split_gemm, cudaFuncAttributeMaxDynamicSharedMemorySize, SMEM_G);
    cudaFuncSetAttribute(bc_g2,         cudaFuncAttributeMaxDynamicSharedMemorySize, G2_SMEM);

    // prep
    bc_tw<<<1, 128>>>();
    bc_build_fj<<<2048, 256>>>(Dv);
    bc_build_op<<<256, 256>>>(W);
    bc_build_b3<<<64, 256>>>();
    // G1: x -> X1 (bufA)
    bc_split_gemm<<<dim3(32, 32), 288, SMEM_G>>>(tm_x, tm_fh, tm_fl, (float*)pA, nullptr);
    // T1: X1 (bufA) -> Xg (bufB)   [j,b,fs] -> [fs,b,j]  (float2)
    bc_transpose<<<dim3(4096, 2), 256>>>((const float2*)pA, (float2*)pB,
                                         262144, 64, 131072, 32, 2);
    // G2: Xg (bufB) -> C (bufA)
    bc_g2<<<dim3(16, 64), 256, G2_SMEM>>>(tm_xg, tm_op, (float*)pA);
    // T2: C (bufA) -> Z (bufB)     [fs,b,i] -> [b,i,fs]  (float2)
    bc_transpose<<<dim3(4096, 2), 256>>>((const float2*)pA, (float2*)pB,
                                         131072, 32, 64, 2048, 1);
    // G3: Z (bufB) -> out (+bias)
    bc_split_gemm<<<dim3(1024, 1), 288, SMEM_G>>>(tm_z, tm_b3h, tm_b3l, out, bias);
}

// round 9
// speedup vs baseline: 3.1314x; 1.3537x over previous
#include <cuda_runtime.h>
#include <cuda.h>
#include <cstdint>
#include <cstdio>
#include <math.h>

// ============================================================================
// BlockCirculant via DFT factorization (63x fewer FLOPs than dense GEMM):
//   out[b, i*128+t] = ifft_t( sum_j fft(x_d block j) * conj(fft(W[i,j])) ) + bias
// Pipeline (all GEMMs legacy mma.sync m16n8k8 tf32; A rna-rounded in-register,
// B rna-prebuilt -> single-pass tf32, no 3x split; error budget ~3.3e-4):
//   P : twiddles, F_j (fwd DFT * D), Op[fs] (64x64 per-freq mix), B3 (inv DFT)
//   G1: X1[j][b][n]    = x[b][j*128+s] @ F_j[n][s]^T       (K=128)
//   T1: Xg[fs][b][2j+c] = X1[j][b][2fs+c]                  (float2 transpose)
//   G2: C[fs][b][2i+c]  = Xg[fs][b][.] @ Op[fs]^T          (K=64)
//   T2: Z[b*32+i][2fs+c] = C[fs][b][2i+c]                  (float2 transpose)
//   G3: out[r][t]       = Z[r][.] @ B3[t][.]^T + bias      (K=128)
// Freq packing: n = 2*fs + c; slot fs=0 carries (f=0, f=64[Nyquist]) real bins.
// G1/G3 share one kernel: CTA tile 256x128xK128, 8 warps (64x64) + TMA warp.
// ============================================================================

static constexpr int DIMN = 4096;

__device__ float  g_bufA[(size_t)DIMN * DIMN];
__device__ float  g_bufB[(size_t)DIMN * DIMN];
__device__ float  g_Fj[32 * 128 * 128];
__device__ float  g_Op[64 * 64 * 64];
__device__ float  g_B3[128 * 128];
__device__ float2 g_tw[128];

// ------------------------------------------------------------ PTX helpers
__device__ __forceinline__ uint32_t smem_u32(const void* p) {
    uint32_t a;
    asm("{ .reg .u64 t; cvta.to.shared.u64 t, %1; cvt.u32.u64 %0, t; }"
        : "=r"(a) : "l"(p));
    return a;
}
__device__ __forceinline__ uint32_t elect_one() {
    uint32_t pred;
    asm volatile(
        "{\n\t.reg .pred p;\n\telect.sync _|p, 0xFFFFFFFF;\n\t"
        "selp.b32 %0, 1, 0, p;\n\t}" : "=r"(pred));
    return pred;
}
#define MBARRIER_INIT(addr, cnt) \
    asm volatile("mbarrier.init.shared.b64 [%0], %1;" \
                 :: "r"((uint32_t)(addr)), "r"((uint32_t)(cnt)) : "memory")
#define MBARRIER_EXPECT_TX(addr, bytes) \
    asm volatile("mbarrier.arrive.expect_tx.shared.b64 _, [%0], %1;" \
                 :: "r"((uint32_t)(addr)), "r"((uint32_t)(bytes)) : "memory")
#define MBARRIER_WAIT_PARITY(addr, parity) do {                                  \
    uint32_t _mbar = (uint32_t)(addr);                                           \
    uint32_t _par  = (uint32_t)(parity);                                         \
    uint32_t _done;                                                              \
    asm volatile(                                                                \
        "{\n\t.reg .pred p;\n\t"                                                 \
        "mbarrier.try_wait.parity.acquire.cta.shared::cta.b64 p, [%1], %2;\n\t"  \
        "selp.b32 %0, 1, 0, p;\n\t}"                                             \
        : "=r"(_done) : "r"(_mbar), "r"(_par) : "memory");                       \
    if (!_done) {                                                                \
        asm volatile(                                                            \
            "{\n\t.reg .pred P1;\n\t"                                            \
            "WAIT_LOOP_%=:\n\t"                                                  \
            "mbarrier.try_wait.parity.acquire.cta.shared::cta.b64 P1, [%0], %1, 0x989680;\n\t" \
            "@P1 bra.uni WAIT_DONE_%=;\n\t"                                      \
            "bra.uni WAIT_LOOP_%=;\n\t"                                          \
            "WAIT_DONE_%=:\n\t}"                                                 \
            :: "r"(_mbar), "r"(_par) : "memory");                                \
    }                                                                            \
} while (0)
#define TMA_LOAD_2D(smem_addr, tmap, cx, cy, mbar)                               \
    asm volatile(                                                                \
        "cp.async.bulk.tensor.2d.shared::cta.global.tile.mbarrier::complete_tx::bytes " \
        "[%0], [%1, {%2, %3}], [%4];"                                            \
        :: "r"((uint32_t)(smem_addr)), "l"(tmap),                                \
           "r"((int32_t)(cx)), "r"((int32_t)(cy)),                               \
           "r"((uint32_t)(mbar)) : "memory")
#define LDSM_X4(d0, d1, d2, d3, addr)                                            \
    asm volatile("ldmatrix.sync.aligned.m8n8.x4.shared.b16 {%0,%1,%2,%3}, [%4];" \
                 : "=r"(d0), "=r"(d1), "=r"(d2), "=r"(d3) : "r"(addr))

__device__ __forceinline__ void mma_tf32(float* c, const uint32_t* a,
                                         const uint32_t* b) {
    asm volatile(
        "mma.sync.aligned.m16n8k8.row.col.f32.tf32.tf32.f32 "
        "{%0,%1,%2,%3}, {%4,%5,%6,%7}, {%8,%9}, {%0,%1,%2,%3};"
        : "+f"(c[0]), "+f"(c[1]), "+f"(c[2]), "+f"(c[3])
        : "r"(a[0]), "r"(a[1]), "r"(a[2]), "r"(a[3]), "r"(b[0]), "r"(b[1]));
}
__device__ __forceinline__ float tf32r(float v) {
    uint32_t u;
    asm("cvt.rna.tf32.f32 %0, %1;" : "=r"(u) : "f"(v));
    return __uint_as_float(u);
}

// ------------------------------------------------------------ prep kernels
__global__ void bc_tw() {
    int t = threadIdx.x;
    double ang = (3.14159265358979323846 / 64.0) * t;   // 2*pi*t/128
    g_tw[t] = make_float2((float)cos(ang), (float)sin(ang));
}

// F_j[j][n][s] = F1[n][s] * D[j*128+s], rna-rounded to tf32
__global__ void bc_build_fj(const float* __restrict__ Dvec) {
    int idx = blockIdx.x * 256 + threadIdx.x;      // 0..524287
    int j = idx >> 14;
    int n = (idx >> 7) & 127;
    int s = idx & 127;
    float base;
    if (n == 0)      base = 1.0f;
    else if (n == 1) base = (s & 1) ? -1.0f : 1.0f;           // f=64 (Nyquist)
    else {
        int f = n >> 1;
        float2 w = g_tw[(f * s) & 127];
        base = (n & 1) ? w.y : w.x;                           // sin : cos
    }
    g_Fj[idx] = tf32r(base * Dvec[j * 128 + s]);
}

// Op[fs][n=2i+c][k=2j+c'] from aW/bW of W[i][j][.]
__global__ void bc_build_op(const float* __restrict__ W) {
    int tid = blockIdx.x * 256 + threadIdx.x;      // 0..65535
    int fs = tid >> 10;
    int i  = (tid >> 5) & 31;
    int j  = tid & 31;
    const float* w = W + (i * 32 + j) * 128;
    float* op = g_Op + (size_t)fs * 4096;          // [64][64] slab
    if (fs == 0) {
        float a0 = 0.f, a64 = 0.f;
        for (int u = 0; u < 128; u++) {
            float wu = w[u];
            a0  += wu;
            a64 += (u & 1) ? -wu : wu;
        }
        op[(2 * i) * 64 + 2 * j]         = tf32r(a0);
        op[(2 * i) * 64 + 2 * j + 1]     = 0.f;
        op[(2 * i + 1) * 64 + 2 * j]     = 0.f;
        op[(2 * i + 1) * 64 + 2 * j + 1] = tf32r(a64);
    } else {
        float aw = 0.f, bw = 0.f;
        for (int u = 0; u < 128; u++) {
            float2 t = g_tw[(fs * u) & 127];
            float wu = w[u];
            aw += wu * t.x;
            bw += wu * t.y;
        }
        // Y_re = aX*aW + bX*bW ; Y_im = aX*bW - bX*aW
        op[(2 * i) * 64 + 2 * j]         = tf32r(aw);
        op[(2 * i) * 64 + 2 * j + 1]     = tf32r(bw);
        op[(2 * i + 1) * 64 + 2 * j]     = tf32r(bw);
        op[(2 * i + 1) * 64 + 2 * j + 1] = tf32r(-aw);
    }
}

// B3[t][n'] inverse transform, rna-rounded
__global__ void bc_build_b3() {
    int idx = blockIdx.x * 256 + threadIdx.x;      // 0..16383
    int t = idx >> 7;
    int n = idx & 127;
    float v;
    if (n == 0)      v = 1.0f / 128.0f;
    else if (n == 1) v = ((t & 1) ? -1.0f : 1.0f) / 128.0f;
    else {
        int f = n >> 1;
        float2 w = g_tw[(f * t) & 127];
        v = ((n & 1) ? -w.y : w.x) * (2.0f / 128.0f);   // cos(+), sin(-)
    }
    g_B3[idx] = tf32r(v);
}

// ------------------------------------------------------------ main GEMM
// C[256 x 128] = A[256 x 128] @ B^T, K=128 (4 chunks of 32), single tf32
// with in-register rna rounding of A. 288 thr: 8 compute warps (64x64 each)
// + TMA warp. G1: grid(16,32) A=x, B=Fj, out=X1. G3: grid(512,1) A=Z, B=B3,
// out=out with bias.
static constexpr int G_ABYTES = 256 * 32 * 4;            // 32 KB
static constexpr int G_BBYTES = 128 * 32 * 4;            // 16 KB
static constexpr int G_STAGE  = G_ABYTES + G_BBYTES;     // 48 KB
static constexpr int SMEM_G   = 2048 + 4 * G_STAGE;      // ~194 KB

__global__ void __launch_bounds__(288, 1)
bc_gemm_tf32(const __grid_constant__ CUtensorMap tma_a,
             const __grid_constant__ CUtensorMap tma_b,
             float* __restrict__ outp,
             const float* __restrict__ bias) {
    extern __shared__ char smem[];
    const uint32_t raw      = smem_u32(smem);
    const uint32_t bar_full = (raw + 15u) & ~7u;                 // 4 barriers
    const uint32_t tiles    = (raw + 1024u + 1023u) & ~1023u;

    const int tid  = threadIdx.x;
    const int wid  = tid >> 5;
    const int lane = tid & 31;
    const int mt   = blockIdx.x;
    const int jb   = blockIdx.y;

    if (tid == 0) {
        for (int s = 0; s < 4; s++) MBARRIER_INIT(bar_full + 8 * s, 1);
        asm volatile("fence.proxy.async.shared::cta;" ::: "memory");
    }
    __syncthreads();

    if (wid == 8) {
        if (elect_one()) {
            for (int kt = 0; kt < 4; kt++) {       // 4 stages = 4 k-iters
                MBARRIER_EXPECT_TX(bar_full + 8 * kt, G_STAGE);
                uint32_t dst = tiles + kt * G_STAGE;
                TMA_LOAD_2D(dst,            &tma_a, jb * 128 + kt * 32, mt * 256, bar_full + 8 * kt);
                TMA_LOAD_2D(dst + G_ABYTES, &tma_b, kt * 32,            jb * 128, bar_full + 8 * kt);
            }
        }
        return;
    }

    const int mo = (wid & 3) * 64;   // 4 warp rows (M=256)
    const int no = (wid >> 2) * 64;  // 2 warp cols (N=128)

    // ldmatrix offsets (SW128: 16B chunk ^= row&7; mo/no mult of 8 -> row&7==rr)
    uint32_t offA[4], offB[4];
    {
        const int t = lane >> 3, rr = lane & 7;
#pragma unroll
        for (int ks = 0; ks < 4; ks++) {
            int rowA = mo + (t & 1) * 8 + rr;
            int chA  = ks * 2 + (t >> 1);
            offA[ks] = rowA * 128 + ((chA ^ rr) << 4);
            int rowB = no + (t >> 1) * 8 + rr;
            int chB  = ks * 2 + (t & 1);
            offB[ks] = rowB * 128 + ((chB ^ rr) << 4);
        }
    }

    float c[4][8][4];
#pragma unroll
    for (int i = 0; i < 4; i++)
#pragma unroll
        for (int j = 0; j < 8; j++)
#pragma unroll
            for (int q = 0; q < 4; q++) c[i][j][q] = 0.0f;

#pragma unroll 1
    for (int kt = 0; kt < 4; kt++) {
        MBARRIER_WAIT_PARITY(bar_full + 8 * kt, 0);
        const uint32_t sa = tiles + kt * G_STAGE;
        const uint32_t sb = sa + G_ABYTES;
#pragma unroll
        for (int ks = 0; ks < 4; ks++) {
            uint32_t a[4][4], b[8][2];
#pragma unroll
            for (int i = 0; i < 4; i++)
                LDSM_X4(a[i][0], a[i][1], a[i][2], a[i][3],
                        sa + offA[ks] + i * 2048);
#pragma unroll
            for (int p = 0; p < 4; p++)
                LDSM_X4(b[2 * p][0], b[2 * p][1], b[2 * p + 1][0], b[2 * p + 1][1],
                        sb + offB[ks] + p * 2048);
            // rna-round A in-register (fma pipe is idle; keeps error minimal)
#pragma unroll
            for (int i = 0; i < 4; i++)
#pragma unroll
                for (int q = 0; q < 4; q++) {
                    float v = __uint_as_float(a[i][q]);
                    asm("cvt.rna.tf32.f32 %0, %1;" : "=r"(a[i][q]) : "f"(v));
                }
#pragma unroll
            for (int i = 0; i < 4; i++)
#pragma unroll
                for (int j = 0; j < 8; j++)
                    mma_tf32(c[i][j], a[i], b[j]);
        }
    }

    // epilogue (ldc = 128); bias indexed by (row & 31)*128 + col (G3 only)
    const size_t rowbase = (size_t)jb * 4096 + (size_t)mt * 256;
    const int g   = lane >> 2;
    const int tig = lane & 3;
#pragma unroll
    for (int i = 0; i < 4; i++) {
        const int r0l = mo + i * 16 + g;
        float* o0 = outp + (rowbase + r0l) * 128;
        float* o1 = o0 + 8 * 128;
#pragma unroll
        for (int j = 0; j < 8; j++) {
            const int col = no + j * 8 + tig * 2;
            float2 v0 = {c[i][j][0], c[i][j][1]};
            float2 v1 = {c[i][j][2], c[i][j][3]};
            if (bias) {
                const float* b0 = bias + (r0l & 31) * 128 + col;
                const float* b1 = bias + ((r0l + 8) & 31) * 128 + col;
                v0.x += b0[0]; v0.y += b0[1];
                v1.x += b1[0]; v1.y += b1[1];
            }
            *reinterpret_cast<float2*>(o0 + col) = v0;
            *reinterpret_cast<float2*>(o1 + col) = v1;
        }
    }
}

// ------------------------------------------------------------ G2 kernel
// Per fs: C[256 x 64] = Xg[256 x 64] @ Op[fs]^T, K=64 (two 32-col halves).
// 256 thr = 8 compute warps (warp tile 32x64); thread 0 issues TMA.
static constexpr int G2_SMEM = 2048 + 81920;

__global__ void __launch_bounds__(256, 2)
bc_g2(const __grid_constant__ CUtensorMap tma_xg,
      const __grid_constant__ CUtensorMap tma_op,
      float* __restrict__ outp) {
    extern __shared__ char smem[];
    const uint32_t raw   = smem_u32(smem);
    const uint32_t bar   = (raw + 15u) & ~7u;
    const uint32_t tiles = (raw + 1024u + 1023u) & ~1023u;

    const int tid  = threadIdx.x;
    const int w    = tid >> 5;
    const int lane = tid & 31;
    const int mt   = blockIdx.x;     // 16 b-tiles of 256
    const int fs   = blockIdx.y;     // 64 freq slots

    if (tid == 0) {
        MBARRIER_INIT(bar, 1);
        asm volatile("fence.proxy.async.shared::cta;" ::: "memory");
    }
    __syncthreads();
    if (tid == 0) {
        MBARRIER_EXPECT_TX(bar, 81920);
        int ya = fs * 4096 + mt * 256;
        TMA_LOAD_2D(tiles,         &tma_xg, 0,  ya,      bar);
        TMA_LOAD_2D(tiles + 32768, &tma_xg, 32, ya,      bar);
        TMA_LOAD_2D(tiles + 65536, &tma_op, 0,  fs * 64, bar);
        TMA_LOAD_2D(tiles + 73728, &tma_op, 32, fs * 64, bar);
    }

    uint32_t offA[4], offB[4];
    {
        const int t = lane >> 3, rr = lane & 7;
#pragma unroll
        for (int kk = 0; kk < 4; kk++) {
            int rowA = w * 32 + (t & 1) * 8 + rr;
            int chA  = kk * 2 + (t >> 1);
            offA[kk] = rowA * 128 + ((chA ^ rr) << 4);
            int rowB = (t >> 1) * 8 + rr;
            int chB  = kk * 2 + (t & 1);
            offB[kk] = rowB * 128 + ((chB ^ rr) << 4);
        }
    }

    float c[2][8][4];
#pragma unroll
    for (int i = 0; i < 2; i++)
#pragma unroll
        for (int j = 0; j < 8; j++)
#pragma unroll
            for (int q = 0; q < 4; q++) c[i][j][q] = 0.0f;

    MBARRIER_WAIT_PARITY(bar, 0);

#pragma unroll
    for (int h = 0; h < 2; h++) {
        const uint32_t sa = tiles + h * 32768;
        const uint32_t sb = tiles + 65536 + h * 8192;
#pragma unroll
        for (int kk = 0; kk < 4; kk++) {
            uint32_t a[2][4], b[8][2];
#pragma unroll
            for (int i = 0; i < 2; i++)
                LDSM_X4(a[i][0], a[i][1], a[i][2], a[i][3],
                        sa + offA[kk] + i * 2048);
#pragma unroll
            for (int np = 0; np < 4; np++)
                LDSM_X4(b[2 * np][0], b[2 * np][1], b[2 * np + 1][0], b[2 * np + 1][1],
                        sb + offB[kk] + np * 2048);
#pragma unroll
            for (int i = 0; i < 2; i++)
#pragma unroll
                for (int q = 0; q < 4; q++) {
                    float v = __uint_as_float(a[i][q]);
                    asm("cvt.rna.tf32.f32 %0, %1;" : "=r"(a[i][q]) : "f"(v));
                }
#pragma unroll
            for (int i = 0; i < 2; i++)
#pragma unroll
                for (int j = 0; j < 8; j++)
                    mma_tf32(c[i][j], a[i], b[j]);
        }
    }

    // epilogue: C[fs][b][n], row = mt*256 + w*32 + ..., ld = 64
    const size_t base = (size_t)fs * 262144 + ((size_t)mt * 256 + w * 32) * 64;
    const int g   = lane >> 2;
    const int tig = lane & 3;
#pragma unroll
    for (int i = 0; i < 2; i++) {
        float* o0 = outp + base + (i * 16 + g) * 64;
        float* o1 = o0 + 8 * 64;
#pragma unroll
        for (int j = 0; j < 8; j++) {
            const int col = j * 8 + tig * 2;
            *reinterpret_cast<float2*>(o0 + col) = make_float2(c[i][j][0], c[i][j][1]);
            *reinterpret_cast<float2*>(o1 + col) = make_float2(c[i][j][2], c[i][j][3]);
        }
    }
}

// ------------------------------------------------------------ transpose
// dst[b*dB + q*dQ + p] = src[p*sP + b*sB + q]   (float2 elements)
__global__ void __launch_bounds__(256)
bc_transpose(const float2* __restrict__ src, float2* __restrict__ dst,
             int sP, int sB, int dQ, int dB, int qtiles) {
    __shared__ float sx[32][33];
    __shared__ float sy[32][33];
    const int b  = blockIdx.x;
    const int pt = blockIdx.y / qtiles;
    const int qt = blockIdx.y % qtiles;
    const int tx = threadIdx.x & 31;
    const int ty = threadIdx.x >> 5;   // 0..7
    const float2* s = src + (size_t)b * sB + (size_t)(pt * 32) * sP + qt * 32;
    float2*       d = dst + (size_t)b * dB + (size_t)(qt * 32) * dQ + pt * 32;
#pragma unroll
    for (int k = 0; k < 4; k++) {
        int p = ty + k * 8;
        float2 v = s[(size_t)p * sP + tx];
        sx[p][tx] = v.x;
        sy[p][tx] = v.y;
    }
    __syncthreads();
#pragma unroll
    for (int k = 0; k < 4; k++) {
        int q = ty + k * 8;
        d[(size_t)q * dQ + tx] = make_float2(sx[tx][q], sy[tx][q]);
    }
}

// ------------------------------------------------------------ host launch
extern "C" void kernel_launch(void* const* d_in, const int* in_sizes, int n_in,
                              void* d_out, int out_size) {
    const float* x    = (const float*)d_in[0];
    const float* W    = (const float*)d_in[1];
    const float* Dv   = (const float*)d_in[2];
    const float* bias = (const float*)d_in[3];
    float* out        = (float*)d_out;

    void *pA, *pB, *pF, *pOp, *pB3;
    cudaGetSymbolAddress(&pA,  g_bufA);
    cudaGetSymbolAddress(&pB,  g_bufB);
    cudaGetSymbolAddress(&pF,  g_Fj);
    cudaGetSymbolAddress(&pOp, g_Op);
    cudaGetSymbolAddress(&pB3, g_B3);

    typedef CUresult (*EncodeFn)(CUtensorMap*, CUtensorMapDataType, cuuint32_t, void*,
                                 const cuuint64_t*, const cuuint64_t*, const cuuint32_t*,
                                 const cuuint32_t*, CUtensorMapInterleave, CUtensorMapSwizzle,
                                 CUtensorMapL2promotion, CUtensorMapFloatOOBfill);
    void* fn = nullptr;
    cudaDriverEntryPointQueryResult qr;
    cudaGetDriverEntryPoint("cuTensorMapEncodeTiled", &fn, cudaEnableDefault, &qr);
    EncodeFn encode = (EncodeFn)fn;
    if (!encode) { fprintf(stderr, "no cuTensorMapEncodeTiled\n"); return; }

    auto enc2d = [&](CUtensorMap* tm, void* ptr, uint64_t cols, uint64_t rows,
                     uint32_t bx, uint32_t by) {
        cuuint64_t dims[2]    = {cols, rows};
        cuuint64_t strides[1] = {cols * sizeof(float)};
        cuuint32_t box[2]     = {bx, by};
        cuuint32_t es[2]      = {1, 1};
        encode(tm, CU_TENSOR_MAP_DATA_TYPE_FLOAT32, 2, ptr, dims, strides, box, es,
               CU_TENSOR_MAP_INTERLEAVE_NONE, CU_TENSOR_MAP_SWIZZLE_128B,
               CU_TENSOR_MAP_L2_PROMOTION_L2_128B, CU_TENSOR_MAP_FLOAT_OOB_FILL_NONE);
    };

    CUtensorMap tm_x, tm_f, tm_z, tm_b3, tm_xg, tm_op;
    enc2d(&tm_x,  (void*)x, 4096, 4096,   32, 256);   // G1 A
    enc2d(&tm_f,  pF,       128,  4096,   32, 128);   // G1 B (Fj)
    enc2d(&tm_z,  pB,       128,  131072, 32, 256);   // G3 A (Z in bufB)
    enc2d(&tm_b3, pB3,      128,  128,    32, 128);   // G3 B
    enc2d(&tm_xg, pB,       64,   262144, 32, 256);   // G2 A (Xg in bufB)
    enc2d(&tm_op, pOp,      64,   4096,   32, 64);    // G2 B

    cudaFuncSetAttribute(bc_gemm_tf32, cudaFuncAttributeMaxDynamicSharedMemorySize, SMEM_G);
    cudaFuncSetAttribute(bc_g2,        cudaFuncAttributeMaxDynamicSharedMemorySize, G2_SMEM);

    // prep
    bc_tw<<<1, 128>>>();
    bc_build_fj<<<2048, 256>>>(Dv);
    bc_build_op<<<256, 256>>>(W);
    bc_build_b3<<<64, 256>>>();
    // G1: x -> X1 (bufA)
    bc_gemm_tf32<<<dim3(16, 32), 288, SMEM_G>>>(tm_x, tm_f, (float*)pA, nullptr);
    // T1: X1 (bufA) -> Xg (bufB)   [j,b,fs] -> [fs,b,j]  (float2)
    bc_transpose<<<dim3(4096, 2), 256>>>((const float2*)pA, (float2*)pB,
                                         262144, 64, 131072, 32, 2);
    // G2: Xg (bufB) -> C (bufA)
    bc_g2<<<dim3(16, 64), 256, G2_SMEM>>>(tm_xg, tm_op, (float*)pA);
    // T2: C (bufA) -> Z (bufB)     [fs,b,i] -> [b,i,fs]  (float2)
    bc_transpose<<<dim3(4096, 2), 256>>>((const float2*)pA, (float2*)pB,
                                         131072, 32, 64, 2048, 1);
    // G3: Z (bufB) -> out (+bias)
    bc_gemm_tf32<<<dim3(512, 1), 288, SMEM_G>>>(tm_z, tm_b3, out, bias);
}

// round 12
// speedup vs baseline: 3.1976x; 1.0211x over previous
#include <cuda_runtime.h>
#include <cuda.h>
#include <cstdint>
#include <cstdio>
#include <math.h>

// ============================================================================
// BlockCirculant via DFT factorization (63x fewer FLOPs than dense GEMM):
//   out[b, i*128+t] = ifft_t( sum_j fft(x_d block j) * conj(fft(W[i,j])) ) + bias
// All GEMMs legacy mma.sync m16n8k8 tf32 (A rna-rounded in-register, B
// rna-prebuilt). Pipeline:
//   P : one merged prep kernel (F_j, Op[fs], B3) via inline sincospif
//   G1: X1[j][b][n]     = x[b][j*128+s] @ F_j[n][s]^T      (K=128)
//   T1: Xg[fs][b][2j+c] = X1[j][b][2fs+c]                  (float2 transpose)
//   G2: C[fs][b][2i+c]  = Xg[fs][b][.] @ Op[fs]^T          (K=64)
//   T2: Z[b*32+i][2fs+c] = C[fs][b][2i+c]                  (float2 transpose)
//   G3: out[r][t]       = Z[r][.] @ B3[t][.]^T + bias      (K=128)
// G1/G3 share one kernel: CTA 128x128xK128, 2-stage TMA pipeline, 8 compute
// warps (64x32) + producer warp, 2 CTAs/SM to hide TMA head + store tail.
// Freq packing: n = 2*fs + c; slot fs=0 carries (f=0, f=64[Nyquist]) real bins.
// ============================================================================

static constexpr int DIMN = 4096;

__device__ float g_bufA[(size_t)DIMN * DIMN];
__device__ float g_bufB[(size_t)DIMN * DIMN];
__device__ float g_Fj[32 * 128 * 128];
__device__ float g_Op[64 * 64 * 64];
__device__ float g_B3[128 * 128];

// ------------------------------------------------------------ PTX helpers
__device__ __forceinline__ uint32_t smem_u32(const void* p) {
    uint32_t a;
    asm("{ .reg .u64 t; cvta.to.shared.u64 t, %1; cvt.u32.u64 %0, t; }"
        : "=r"(a) : "l"(p));
    return a;
}
__device__ __forceinline__ uint32_t elect_one() {
    uint32_t pred;
    asm volatile(
        "{\n\t.reg .pred p;\n\telect.sync _|p, 0xFFFFFFFF;\n\t"
        "selp.b32 %0, 1, 0, p;\n\t}" : "=r"(pred));
    return pred;
}
#define MBARRIER_INIT(addr, cnt) \
    asm volatile("mbarrier.init.shared.b64 [%0], %1;" \
                 :: "r"((uint32_t)(addr)), "r"((uint32_t)(cnt)) : "memory")
#define MBARRIER_ARRIVE(addr) \
    asm volatile("mbarrier.arrive.shared.b64 _, [%0];" \
                 :: "r"((uint32_t)(addr)) : "memory")
#define MBARRIER_EXPECT_TX(addr, bytes) \
    asm volatile("mbarrier.arrive.expect_tx.shared.b64 _, [%0], %1;" \
                 :: "r"((uint32_t)(addr)), "r"((uint32_t)(bytes)) : "memory")
#define MBARRIER_WAIT_PARITY(addr, parity) do {                                  \
    uint32_t _mbar = (uint32_t)(addr);                                           \
    uint32_t _par  = (uint32_t)(parity);                                         \
    uint32_t _done;                                                              \
    asm volatile(                                                                \
        "{\n\t.reg .pred p;\n\t"                                                 \
        "mbarrier.try_wait.parity.acquire.cta.shared::cta.b64 p, [%1], %2;\n\t"  \
        "selp.b32 %0, 1, 0, p;\n\t}"                                             \
        : "=r"(_done) : "r"(_mbar), "r"(_par) : "memory");                       \
    if (!_done) {                                                                \
        asm volatile(                                                            \
            "{\n\t.reg .pred P1;\n\t"                                            \
            "WAIT_LOOP_%=:\n\t"                                                  \
            "mbarrier.try_wait.parity.acquire.cta.shared::cta.b64 P1, [%0], %1, 0x989680;\n\t" \
            "@P1 bra.uni WAIT_DONE_%=;\n\t"                                      \
            "bra.uni WAIT_LOOP_%=;\n\t"                                          \
            "WAIT_DONE_%=:\n\t}"                                                 \
            :: "r"(_mbar), "r"(_par) : "memory");                                \
    }                                                                            \
} while (0)
#define TMA_LOAD_2D(smem_addr, tmap, cx, cy, mbar)                               \
    asm volatile(                                                                \
        "cp.async.bulk.tensor.2d.shared::cta.global.tile.mbarrier::complete_tx::bytes " \
        "[%0], [%1, {%2, %3}], [%4];"                                            \
        :: "r"((uint32_t)(smem_addr)), "l"(tmap),                                \
           "r"((int32_t)(cx)), "r"((int32_t)(cy)),                               \
           "r"((uint32_t)(mbar)) : "memory")
#define LDSM_X4(d0, d1, d2, d3, addr)                                            \
    asm volatile("ldmatrix.sync.aligned.m8n8.x4.shared.b16 {%0,%1,%2,%3}, [%4];" \
                 : "=r"(d0), "=r"(d1), "=r"(d2), "=r"(d3) : "r"(addr))

__device__ __forceinline__ void mma_tf32(float* c, const uint32_t* a,
                                         const uint32_t* b) {
    asm volatile(
        "mma.sync.aligned.m16n8k8.row.col.f32.tf32.tf32.f32 "
        "{%0,%1,%2,%3}, {%4,%5,%6,%7}, {%8,%9}, {%0,%1,%2,%3};"
        : "+f"(c[0]), "+f"(c[1]), "+f"(c[2]), "+f"(c[3])
        : "r"(a[0]), "r"(a[1]), "r"(a[2]), "r"(a[3]), "r"(b[0]), "r"(b[1]));
}
__device__ __forceinline__ float tf32r(float v) {
    uint32_t u;
    asm("cvt.rna.tf32.f32 %0, %1;" : "=r"(u) : "f"(v));
    return __uint_as_float(u);
}
// cos/sin of 2*pi*m/128 = pi*(m/64), m in [0,128)
__device__ __forceinline__ float2 twiddle(int m) {
    float s, c;
    sincospif((float)m * (1.0f / 64.0f), &s, &c);
    return make_float2(c, s);
}

// ------------------------------------------------------------ merged prep
// blocks [0,2048): F_j ; [2048,2304): Op ; [2304,2368): B3
__global__ void __launch_bounds__(256)
bc_prep(const float* __restrict__ W, const float* __restrict__ Dvec) {
    const int bx = blockIdx.x;
    if (bx < 2048) {
        // F_j[j][n][s] = F1[n][s] * D[j*128+s], tf32-rounded
        int idx = bx * 256 + threadIdx.x;          // 0..524287
        int j = idx >> 14;
        int n = (idx >> 7) & 127;
        int s = idx & 127;
        float base;
        if (n == 0)      base = 1.0f;
        else if (n == 1) base = (s & 1) ? -1.0f : 1.0f;       // f=64 (Nyquist)
        else {
            float2 w = twiddle(((n >> 1) * s) & 127);
            base = (n & 1) ? w.y : w.x;                       // sin : cos
        }
        g_Fj[idx] = tf32r(base * Dvec[j * 128 + s]);
    } else if (bx < 2304) {
        // Op[fs][2i+c][2j+c'] from aW/bW of W[i][j][.]
        int tid = (bx - 2048) * 256 + threadIdx.x; // 0..65535
        int fs = tid >> 10;
        int i  = (tid >> 5) & 31;
        int j  = tid & 31;
        const float* w = W + (i * 32 + j) * 128;
        float* op = g_Op + (size_t)fs * 4096;
        if (fs == 0) {
            float a0 = 0.f, a64 = 0.f;
            for (int u = 0; u < 128; u++) {
                float wu = w[u];
                a0  += wu;
                a64 += (u & 1) ? -wu : wu;
            }
            op[(2 * i) * 64 + 2 * j]         = tf32r(a0);
            op[(2 * i) * 64 + 2 * j + 1]     = 0.f;
            op[(2 * i + 1) * 64 + 2 * j]     = 0.f;
            op[(2 * i + 1) * 64 + 2 * j + 1] = tf32r(a64);
        } else {
            float aw = 0.f, bw = 0.f;
            for (int u = 0; u < 128; u++) {
                float2 t = twiddle((fs * u) & 127);
                float wu = w[u];
                aw += wu * t.x;
                bw += wu * t.y;
            }
            // Y_re = aX*aW + bX*bW ; Y_im = aX*bW - bX*aW
            op[(2 * i) * 64 + 2 * j]         = tf32r(aw);
            op[(2 * i) * 64 + 2 * j + 1]     = tf32r(bw);
            op[(2 * i + 1) * 64 + 2 * j]     = tf32r(bw);
            op[(2 * i + 1) * 64 + 2 * j + 1] = tf32r(-aw);
        }
    } else {
        // B3[t][n'] inverse transform
        int idx = (bx - 2304) * 256 + threadIdx.x; // 0..16383
        int t = idx >> 7;
        int n = idx & 127;
        float v;
        if (n == 0)      v = 1.0f / 128.0f;
        else if (n == 1) v = ((t & 1) ? -1.0f : 1.0f) / 128.0f;
        else {
            float2 w = twiddle(((n >> 1) * t) & 127);
            v = ((n & 1) ? -w.y : w.x) * (2.0f / 128.0f);     // cos(+), sin(-)
        }
        g_B3[idx] = tf32r(v);
    }
}

// ------------------------------------------------------------ main GEMM
// C[128 x 128] = A[128 x 128] @ B^T, K=128 (4 chunks of 32), 2-stage TMA
// pipeline with backpressure, 2 CTAs/SM. 288 thr: 8 compute warps (64x32)
// + producer warp. G1: grid(32,32) A=x, B=Fj, out=X1. G3: grid(1024,1)
// A=Z, B=B3, out=out with bias.
static constexpr int G_ABYTES = 128 * 32 * 4;            // 16 KB
static constexpr int G_STAGE  = 2 * G_ABYTES;            // A + B = 32 KB
static constexpr int SMEM_G   = 2048 + 2 * G_STAGE;      // 66 KB -> 2 CTAs/SM

__global__ void __launch_bounds__(288, 2)
bc_gemm_tf32(const __grid_constant__ CUtensorMap tma_a,
             const __grid_constant__ CUtensorMap tma_b,
             float* __restrict__ outp,
             const float* __restrict__ bias) {
    extern __shared__ char smem[];
    const uint32_t raw       = smem_u32(smem);
    const uint32_t bar_full  = (raw + 15u) & ~7u;        // 2 barriers
    const uint32_t bar_empty = bar_full + 16;            // 2 barriers
    const uint32_t tiles     = (raw + 1024u + 1023u) & ~1023u;

    const int tid  = threadIdx.x;
    const int wid  = tid >> 5;
    const int lane = tid & 31;
    const int mt   = blockIdx.x;
    const int jb   = blockIdx.y;

    if (tid == 0) {
        for (int s = 0; s < 2; s++) {
            MBARRIER_INIT(bar_full + 8 * s, 1);   // tx-based
            MBARRIER_INIT(bar_empty + 8 * s, 8);  // 8 compute warps
        }
        asm volatile("fence.proxy.async.shared::cta;" ::: "memory");
    }
    __syncthreads();

    if (wid == 8) {
        if (elect_one()) {
            int stage = 0, phase = 1;   // parity 1: first 2 empty-waits pass
            for (int kt = 0; kt < 4; kt++) {
                MBARRIER_WAIT_PARITY(bar_empty + 8 * stage, phase);
                MBARRIER_EXPECT_TX(bar_full + 8 * stage, G_STAGE);
                uint32_t dst = tiles + stage * G_STAGE;
                TMA_LOAD_2D(dst,            &tma_a, jb * 128 + kt * 32, mt * 128, bar_full + 8 * stage);
                TMA_LOAD_2D(dst + G_ABYTES, &tma_b, kt * 32,            jb * 128, bar_full + 8 * stage);
                if (++stage == 2) { stage = 0; phase ^= 1; }
            }
        }
        return;
    }

    const int mo = (wid & 1) * 64;   // 2 warp rows (M=128)
    const int no = (wid >> 1) * 32;  // 4 warp cols (N=128)

    // ldmatrix offsets (SW128: 16B chunk ^= row&7; mo/no mult of 8 -> row&7==rr)
    uint32_t offA[4], offB[4];
    {
        const int t = lane >> 3, rr = lane & 7;
#pragma unroll
        for (int ks = 0; ks < 4; ks++) {
            int rowA = mo + (t & 1) * 8 + rr;
            int chA  = ks * 2 + (t >> 1);
            offA[ks] = rowA * 128 + ((chA ^ rr) << 4);
            int rowB = no + (t >> 1) * 8 + rr;
            int chB  = ks * 2 + (t & 1);
            offB[ks] = rowB * 128 + ((chB ^ rr) << 4);
        }
    }

    float c[4][4][4];
#pragma unroll
    for (int i = 0; i < 4; i++)
#pragma unroll
        for (int j = 0; j < 4; j++)
#pragma unroll
            for (int q = 0; q < 4; q++) c[i][j][q] = 0.0f;

    int stage = 0, phase = 0;
#pragma unroll 1
    for (int kt = 0; kt < 4; kt++) {
        MBARRIER_WAIT_PARITY(bar_full + 8 * stage, phase);
        const uint32_t sa = tiles + stage * G_STAGE;
        const uint32_t sb = sa + G_ABYTES;
#pragma unroll
        for (int ks = 0; ks < 4; ks++) {
            uint32_t a[4][4], b[4][2];
#pragma unroll
            for (int i = 0; i < 4; i++)
                LDSM_X4(a[i][0], a[i][1], a[i][2], a[i][3],
                        sa + offA[ks] + i * 2048);
            LDSM_X4(b[0][0], b[0][1], b[1][0], b[1][1], sb + offB[ks]);
            LDSM_X4(b[2][0], b[2][1], b[3][0], b[3][1], sb + offB[ks] + 2048);
            // rna-round A in-register
#pragma unroll
            for (int i = 0; i < 4; i++)
#pragma unroll
                for (int q = 0; q < 4; q++) {
                    float v = __uint_as_float(a[i][q]);
                    asm("cvt.rna.tf32.f32 %0, %1;" : "=r"(a[i][q]) : "f"(v));
                }
#pragma unroll
            for (int i = 0; i < 4; i++)
#pragma unroll
                for (int j = 0; j < 4; j++)
                    mma_tf32(c[i][j], a[i], b[j]);
        }
        if (elect_one()) MBARRIER_ARRIVE(bar_empty + 8 * stage);
        if (++stage == 2) { stage = 0; phase ^= 1; }
    }

    // epilogue (ldc = 128); bias indexed by (row & 31)*128 + col (G3 only)
    const size_t rowbase = (size_t)jb * 4096 + (size_t)mt * 128;
    const int g   = lane >> 2;
    const int tig = lane & 3;
#pragma unroll
    for (int i = 0; i < 4; i++) {
        const int r0l = mo + i * 16 + g;
        float* o0 = outp + (rowbase + r0l) * 128;
        float* o1 = o0 + 8 * 128;
#pragma unroll
        for (int j = 0; j < 4; j++) {
            const int col = no + j * 8 + tig * 2;
            float2 v0 = {c[i][j][0], c[i][j][1]};
            float2 v1 = {c[i][j][2], c[i][j][3]};
            if (bias) {
                const float* b0 = bias + (r0l & 31) * 128 + col;
                const float* b1 = bias + ((r0l + 8) & 31) * 128 + col;
                v0.x += b0[0]; v0.y += b0[1];
                v1.x += b1[0]; v1.y += b1[1];
            }
            *reinterpret_cast<float2*>(o0 + col) = v0;
            *reinterpret_cast<float2*>(o1 + col) = v1;
        }
    }
}

// ------------------------------------------------------------ G2 kernel
// Per fs: C[256 x 64] = Xg[256 x 64] @ Op[fs]^T, K=64 (two 32-col halves).
// 256 thr = 8 compute warps (warp tile 32x64); thread 0 issues TMA.
static constexpr int G2_SMEM = 2048 + 81920;

__global__ void __launch_bounds__(256, 2)
bc_g2(const __grid_constant__ CUtensorMap tma_xg,
      const __grid_constant__ CUtensorMap tma_op,
      float* __restrict__ outp) {
    extern __shared__ char smem[];
    const uint32_t raw   = smem_u32(smem);
    const uint32_t bar   = (raw + 15u) & ~7u;
    const uint32_t tiles = (raw + 1024u + 1023u) & ~1023u;

    const int tid  = threadIdx.x;
    const int w    = tid >> 5;
    const int lane = tid & 31;
    const int mt   = blockIdx.x;     // 16 b-tiles of 256
    const int fs   = blockIdx.y;     // 64 freq slots

    if (tid == 0) {
        MBARRIER_INIT(bar, 1);
        asm volatile("fence.proxy.async.shared::cta;" ::: "memory");
    }
    __syncthreads();
    if (tid == 0) {
        MBARRIER_EXPECT_TX(bar, 81920);
        int ya = fs * 4096 + mt * 256;
        TMA_LOAD_2D(tiles,         &tma_xg, 0,  ya,      bar);
        TMA_LOAD_2D(tiles + 32768, &tma_xg, 32, ya,      bar);
        TMA_LOAD_2D(tiles + 65536, &tma_op, 0,  fs * 64, bar);
        TMA_LOAD_2D(tiles + 73728, &tma_op, 32, fs * 64, bar);
    }

    uint32_t offA[4], offB[4];
    {
        const int t = lane >> 3, rr = lane & 7;
#pragma unroll
        for (int kk = 0; kk < 4; kk++) {
            int rowA = w * 32 + (t & 1) * 8 + rr;
            int chA  = kk * 2 + (t >> 1);
            offA[kk] = rowA * 128 + ((chA ^ rr) << 4);
            int rowB = (t >> 1) * 8 + rr;
            int chB  = kk * 2 + (t & 1);
            offB[kk] = rowB * 128 + ((chB ^ rr) << 4);
        }
    }

    float c[2][8][4];
#pragma unroll
    for (int i = 0; i < 2; i++)
#pragma unroll
        for (int j = 0; j < 8; j++)
#pragma unroll
            for (int q = 0; q < 4; q++) c[i][j][q] = 0.0f;

    MBARRIER_WAIT_PARITY(bar, 0);

#pragma unroll
    for (int h = 0; h < 2; h++) {
        const uint32_t sa = tiles + h * 32768;
        const uint32_t sb = tiles + 65536 + h * 8192;
#pragma unroll
        for (int kk = 0; kk < 4; kk++) {
            uint32_t a[2][4], b[8][2];
#pragma unroll
            for (int i = 0; i < 2; i++)
                LDSM_X4(a[i][0], a[i][1], a[i][2], a[i][3],
                        sa + offA[kk] + i * 2048);
#pragma unroll
            for (int np = 0; np < 4; np++)
                LDSM_X4(b[2 * np][0], b[2 * np][1], b[2 * np + 1][0], b[2 * np + 1][1],
                        sb + offB[kk] + np * 2048);
#pragma unroll
            for (int i = 0; i < 2; i++)
#pragma unroll
                for (int q = 0; q < 4; q++) {
                    float v = __uint_as_float(a[i][q]);
                    asm("cvt.rna.tf32.f32 %0, %1;" : "=r"(a[i][q]) : "f"(v));
                }
#pragma unroll
            for (int i = 0; i < 2; i++)
#pragma unroll
                for (int j = 0; j < 8; j++)
                    mma_tf32(c[i][j], a[i], b[j]);
        }
    }

    // epilogue: C[fs][b][n], row = mt*256 + w*32 + ..., ld = 64
    const size_t base = (size_t)fs * 262144 + ((size_t)mt * 256 + w * 32) * 64;
    const int g   = lane >> 2;
    const int tig = lane & 3;
#pragma unroll
    for (int i = 0; i < 2; i++) {
        float* o0 = outp + base + (i * 16 + g) * 64;
        float* o1 = o0 + 8 * 64;
#pragma unroll
        for (int j = 0; j < 8; j++) {
            const int col = j * 8 + tig * 2;
            *reinterpret_cast<float2*>(o0 + col) = make_float2(c[i][j][0], c[i][j][1]);
            *reinterpret_cast<float2*>(o1 + col) = make_float2(c[i][j][2], c[i][j][3]);
        }
    }
}

// ------------------------------------------------------------ transpose
// dst[b*dB + q*dQ + p] = src[p*sP + b*sB + q]   (float2 elements)
__global__ void __launch_bounds__(256)
bc_transpose(const float2* __restrict__ src, float2* __restrict__ dst,
             int sP, int sB, int dQ, int dB, int qtiles) {
    __shared__ float sx[32][33];
    __shared__ float sy[32][33];
    const int b  = blockIdx.x;
    const int pt = blockIdx.y / qtiles;
    const int qt = blockIdx.y % qtiles;
    const int tx = threadIdx.x & 31;
    const int ty = threadIdx.x >> 5;   // 0..7
    const float2* s = src + (size_t)b * sB + (size_t)(pt * 32) * sP + qt * 32;
    float2*       d = dst + (size_t)b * dB + (size_t)(qt * 32) * dQ + pt * 32;
#pragma unroll
    for (int k = 0; k < 4; k++) {
        int p = ty + k * 8;
        float2 v = s[(size_t)p * sP + tx];
        sx[p][tx] = v.x;
        sy[p][tx] = v.y;
    }
    __syncthreads();
#pragma unroll
    for (int k = 0; k < 4; k++) {
        int q = ty + k * 8;
        d[(size_t)q * dQ + tx] = make_float2(sx[tx][q], sy[tx][q]);
    }
}

// ------------------------------------------------------------ host launch
extern "C" void kernel_launch(void* const* d_in, const int* in_sizes, int n_in,
                              void* d_out, int out_size) {
    const float* x    = (const float*)d_in[0];
    const float* W    = (const float*)d_in[1];
    const float* Dv   = (const float*)d_in[2];
    const float* bias = (const float*)d_in[3];
    float* out        = (float*)d_out;

    void *pA, *pB, *pF, *pOp, *pB3;
    cudaGetSymbolAddress(&pA,  g_bufA);
    cudaGetSymbolAddress(&pB,  g_bufB);
    cudaGetSymbolAddress(&pF,  g_Fj);
    cudaGetSymbolAddress(&pOp, g_Op);
    cudaGetSymbolAddress(&pB3, g_B3);

    typedef CUresult (*EncodeFn)(CUtensorMap*, CUtensorMapDataType, cuuint32_t, void*,
                                 const cuuint64_t*, const cuuint64_t*, const cuuint32_t*,
                                 const cuuint32_t*, CUtensorMapInterleave, CUtensorMapSwizzle,
                                 CUtensorMapL2promotion, CUtensorMapFloatOOBfill);
    void* fn = nullptr;
    cudaDriverEntryPointQueryResult qr;
    cudaGetDriverEntryPoint("cuTensorMapEncodeTiled", &fn, cudaEnableDefault, &qr);
    EncodeFn encode = (EncodeFn)fn;
    if (!encode) { fprintf(stderr, "no cuTensorMapEncodeTiled\n"); return; }

    auto enc2d = [&](CUtensorMap* tm, void* ptr, uint64_t cols, uint64_t rows,
                     uint32_t bx, uint32_t by) {
        cuuint64_t dims[2]    = {cols, rows};
        cuuint64_t strides[1] = {cols * sizeof(float)};
        cuuint32_t box[2]     = {bx, by};
        cuuint32_t es[2]      = {1, 1};
        encode(tm, CU_TENSOR_MAP_DATA_TYPE_FLOAT32, 2, ptr, dims, strides, box, es,
               CU_TENSOR_MAP_INTERLEAVE_NONE, CU_TENSOR_MAP_SWIZZLE_128B,
               CU_TENSOR_MAP_L2_PROMOTION_L2_128B, CU_TENSOR_MAP_FLOAT_OOB_FILL_NONE);
    };

    CUtensorMap tm_x, tm_f, tm_z, tm_b3, tm_xg, tm_op;
    enc2d(&tm_x,  (void*)x, 4096, 4096,   32, 128);   // G1 A
    enc2d(&tm_f,  pF,       128,  4096,   32, 128);   // G1 B (Fj)
    enc2d(&tm_z,  pB,       128,  131072, 32, 128);   // G3 A (Z in bufB)
    enc2d(&tm_b3, pB3,      128,  128,    32, 128);   // G3 B
    enc2d(&tm_xg, pB,       64,   262144, 32, 256);   // G2 A (Xg in bufB)
    enc2d(&tm_op, pOp,      64,   4096,   32, 64);    // G2 B

    cudaFuncSetAttribute(bc_gemm_tf32, cudaFuncAttributeMaxDynamicSharedMemorySize, SMEM_G);
    cudaFuncSetAttribute(bc_g2,        cudaFuncAttributeMaxDynamicSharedMemorySize, G2_SMEM);

    // prep (merged)
    bc_prep<<<2368, 256>>>(W, Dv);
    // G1: x -> X1 (bufA)
    bc_gemm_tf32<<<dim3(32, 32), 288, SMEM_G>>>(tm_x, tm_f, (float*)pA, nullptr);
    // T1: X1 (bufA) -> Xg (bufB)   [j,b,fs] -> [fs,b,j]  (float2)
    bc_transpose<<<dim3(4096, 2), 256>>>((const float2*)pA, (float2*)pB,
                                         262144, 64, 131072, 32, 2);
    // G2: Xg (bufB) -> C (bufA)
    bc_g2<<<dim3(16, 64), 256, G2_SMEM>>>(tm_xg, tm_op, (float*)pA);
    // T2: C (bufA) -> Z (bufB)     [fs,b,i] -> [b,i,fs]  (float2)
    bc_transpose<<<dim3(4096, 2), 256>>>((const float2*)pA, (float2*)pB,
                                         131072, 32, 64, 2048, 1);
    // G3: Z (bufB) -> out (+bias)
    bc_gemm_tf32<<<dim3(1024, 1), 288, SMEM_G>>>(tm_z, tm_b3, out, bias);
}